// round 17
// baseline (speedup 1.0000x reference)
#include <cuda_runtime.h>
#include <cuda_bf16.h>
#include <math_constants.h>

// Problem constants (from setup_inputs: x [8,4096,64] fp32, k=20)
#define B 8
#define N 4096
#define D 64
#define K 20
#define NQ (B * N)
#define JHALF (N / 2)

// Scratch (allocation-free rule: __device__ globals)
__device__ float        g_sq[NQ];              // squared norms
__device__ int          g_nn[NQ * K];          // merged knn indices
__device__ unsigned int g_kd_part[2][NQ * K];  // partial top-k dist KEYS (u32)
__device__ int          g_ki_part[2][NQ * K];  // partial top-k indices

// ---------------------------------------------------------------------------
// Kernel 1: squared norms per point.  (VERIFIED bit-exact vs reference, R14)
// XLA CPU LLVM loop-vectorizer lowering, VF=4 IC=4, fp-contract on:
//   16 fmla chains stride 16; fold (v0+v1)+(v2+v3) elementwise; faddp pairwise.
// ---------------------------------------------------------------------------
__global__ void sq_kernel(const float* __restrict__ x) {
    int pt = blockIdx.x * blockDim.x + threadIdx.x;
    if (pt >= NQ) return;
    const float4* xp = (const float4*)(x + (size_t)pt * D);

    float ch[16];
#pragma unroll
    for (int c = 0; c < 16; ++c) ch[c] = 0.f;

#pragma unroll
    for (int t = 0; t < 4; ++t) {
#pragma unroll
        for (int v = 0; v < 4; ++v) {
            float4 c4 = xp[4 * t + v];
            ch[4 * v + 0] = fmaf(c4.x, c4.x, ch[4 * v + 0]);
            ch[4 * v + 1] = fmaf(c4.y, c4.y, ch[4 * v + 1]);
            ch[4 * v + 2] = fmaf(c4.z, c4.z, ch[4 * v + 2]);
            ch[4 * v + 3] = fmaf(c4.w, c4.w, ch[4 * v + 3]);
        }
    }

    float a[4];
#pragma unroll
    for (int c = 0; c < 4; ++c) {
        a[c] = __fadd_rn(__fadd_rn(ch[c], ch[c + 4]),
                         __fadd_rn(ch[c + 8], ch[c + 12]));
    }
    g_sq[pt] = __fadd_rn(__fadd_rn(a[0], a[1]), __fadd_rn(a[2], a[3]));
}

// ---------------------------------------------------------------------------
// Kernel 2: split-j partial knn with packed f32x2 FMA + u32 sort keys.
// Arithmetic bit-identical to R14/R15/R16:
//   inner = single sequential fp32 fma chain per candidate, d ascending
//           (each lane of fma.rn.f32x2 is an independent IEEE-rn fp32 fma)
//   dist  = fl(fl(sq_i - 2*inner) + sq_j)
//   ties  = stable ascending index (strict-< on monotonic u32 key)
//
// Shared tile is ELEMENT-MAJOR with XOR swizzle: float (e, j) lives at
//   tile[e*32 + (j ^ (e & 12))]
// so a 16B ld.shared.v2.u64 at column (j0 ^ (e&12)) yields two packed
// candidate-pairs {v_j0[e],v_j0+1[e]} , {v_j0+2[e],v_j0+3[e]}.  Swizzle
// keeps store-side STS at 4-way conflicts; reads are warp-broadcast (N=1).
// ---------------------------------------------------------------------------
#define FMA2(d, a, b)                                                         \
    asm("fma.rn.f32x2 %0, %1, %2, %3;" : "=l"(d) : "l"(a), "l"(b), "l"(d))

__global__ __launch_bounds__(32, 12) void knn_kernel(const float* __restrict__ x) {
    __shared__ float tile[D * 32];          // 64 elems x 32 candidates, 8 KB
    __shared__ float ssq[32];

    const int lane  = threadIdx.x;
    const int cta   = blockIdx.x;           // 0 .. 2*NQ/32 - 1
    const int half  = cta & 1;
    const int qcta  = cta >> 1;             // 0 .. NQ/32 - 1
    const int b     = qcta >> 7;            // N/32 = 128 query-CTAs per batch
    const int i     = ((qcta & 127) << 5) + lane;

    const float*  xb  = x + (size_t)b * N * D;
    const float4* xb4 = (const float4*)xb;

    // Query in registers, scalar array with static indices after unroll
    float qreg[D];
    {
        const float4* xq = (const float4*)(xb + (size_t)i * D);
#pragma unroll
        for (int t = 0; t < D / 4; ++t) {
            float4 c = xq[t];
            qreg[4 * t + 0] = c.x;
            qreg[4 * t + 1] = c.y;
            qreg[4 * t + 2] = c.z;
            qreg[4 * t + 3] = c.w;
        }
    }
    const float sq_i = g_sq[b * N + i];

    // Partial top-k: u32 keys (monotonic in dist), sorted ascending
    unsigned int kdk[K];
    int          ki[K];
#pragma unroll
    for (int t = 0; t < K; ++t) { kdk[t] = 0xFFFFFFFFu; ki[t] = 0x7fffffff; }

    const int sq_base = b * N;
    const int j_lo = half * JHALF;
    const int j_hi = j_lo + JHALF;

    for (int jt = j_lo; jt < j_hi; jt += 32) {
        // Stage 32 candidates: coalesced float4 global loads, swizzled
        // element-major scatter (4-way STS conflicts by construction).
#pragma unroll
        for (int t = 0; t < 16; ++t) {
            int f  = t * 32 + lane;              // flat float4 index
            int j  = f >> 4;
            int tt = f & 15;
            float4 v = xb4[(size_t)jt * 16 + f];
            int e0  = tt * 4;
            int col = j ^ ((tt & 3) * 4);        // (e&12) const over k=0..3
            tile[(e0 + 0) * 32 + col] = v.x;
            tile[(e0 + 1) * 32 + col] = v.y;
            tile[(e0 + 2) * 32 + col] = v.z;
            tile[(e0 + 3) * 32 + col] = v.w;
        }
        ssq[lane] = g_sq[sq_base + jt + lane];
        __syncthreads();

        // 8 candidates per group = 4 packed f32x2 chains (ILP 4x2)
#pragma unroll 1
        for (int j0 = 0; j0 < 32; j0 += 8) {
            unsigned long long acc0 = 0ull, acc1 = 0ull,
                               acc2 = 0ull, acc3 = 0ull;
            // Precomputed swizzled columns for the two quads, one per e&12
            int cA[4], cB[4];
#pragma unroll
            for (int s = 0; s < 4; ++s) {
                cA[s] = (j0    ) ^ (s * 4);
                cB[s] = (j0 + 4) ^ (s * 4);
            }

#pragma unroll
            for (int e = 0; e < D; ++e) {
                const int s = (e >> 2) & 3;      // compile-time after unroll
                const ulonglong2 va =
                    *(const ulonglong2*)&tile[e * 32 + cA[s]];
                const ulonglong2 vb =
                    *(const ulonglong2*)&tile[e * 32 + cB[s]];
                unsigned long long qq;
                asm("mov.b64 %0, {%1, %1};"
                    : "=l"(qq) : "r"(__float_as_uint(qreg[e])));
                FMA2(acc0, qq, va.x);
                FMA2(acc1, qq, va.y);
                FMA2(acc2, qq, vb.x);
                FMA2(acc3, qq, vb.y);
            }

            // Unpack 8 dots (lo lane = lower candidate index)
            float dot[8];
            asm("mov.b64 {%0, %1}, %2;" : "=f"(dot[0]), "=f"(dot[1]) : "l"(acc0));
            asm("mov.b64 {%0, %1}, %2;" : "=f"(dot[2]), "=f"(dot[3]) : "l"(acc1));
            asm("mov.b64 {%0, %1}, %2;" : "=f"(dot[4]), "=f"(dot[5]) : "l"(acc2));
            asm("mov.b64 {%0, %1}, %2;" : "=f"(dot[6]), "=f"(dot[7]) : "l"(acc3));

#pragma unroll
            for (int m = 0; m < 8; ++m) {        // ascending m => stable ties
                // dist = ((sq_i - 2*inner) + sq_j), exact jnp rounding
                float u    = __fmul_rn(2.0f, dot[m]);     // exact (x2)
                float tt2  = __fsub_rn(sq_i, u);
                float dist = __fadd_rn(tt2, ssq[j0 + m]);
                // monotonic u32 key (total order == float order)
                unsigned int fb = __float_as_uint(dist);
                unsigned int kb = fb ^ (0x80000000u |
                                        (unsigned int)((int)fb >> 31));

                if (kb < kdk[K - 1]) {
                    const int jg = jt + j0 + m;
                    // Branchless shift-insert, static indices, ALU-pipe
                    // integer compares (strict > keeps equal keys stable).
#pragma unroll
                    for (int t = K - 1; t >= 0; --t) {
                        bool cur_gt  = kdk[t] > kb;
                        bool prev_gt = (t > 0) ? (kdk[t - 1] > kb) : false;
                        if (cur_gt) {
                            kdk[t] = prev_gt ? kdk[t - 1] : kb;
                            ki[t]  = prev_gt ? ki[t - 1]  : jg;
                        }
                    }
                }
            }
        }
        __syncthreads();
    }

    const int base = (b * N + i) * K;
#pragma unroll
    for (int t = 0; t < K; ++t) {
        g_kd_part[half][base + t] = kdk[t];
        g_ki_part[half][base + t] = ki[t];
    }
}

// ---------------------------------------------------------------------------
// Kernel 2b: merge the two sorted partial top-20 lists per query.
// All half-0 indices < all half-1 indices, so stable ascending-index tie
// order == "pick A when keyA <= keyB".  Exact two-pointer merge on u32 keys.
// ---------------------------------------------------------------------------
__global__ void merge_kernel() {
    int qi = blockIdx.x * blockDim.x + threadIdx.x;
    if (qi >= NQ) return;
    const int base = qi * K;

    unsigned int akd[K], bkd[K];
    int          aki[K], bki[K];
#pragma unroll
    for (int t = 0; t < K; ++t) {
        akd[t] = g_kd_part[0][base + t];
        aki[t] = g_ki_part[0][base + t];
        bkd[t] = g_kd_part[1][base + t];
        bki[t] = g_ki_part[1][base + t];
    }

    int pa = 0, pb = 0;
#pragma unroll
    for (int t = 0; t < K; ++t) {
        bool takeA = (pb >= K) || (pa < K && akd[pa] <= bkd[pb]);
        g_nn[base + t] = takeA ? aki[pa] : bki[pb];
        if (takeA) ++pa; else ++pb;
    }
}

// ---------------------------------------------------------------------------
// Kernel 3: gather + edge-feature construction.
// One warp per output row (b,i,kk): 128 floats = 32 float4, one per lane.
// lane<16  -> x_target chunk ; lane>=16 -> x_neighbor - x_target chunk
// ---------------------------------------------------------------------------
__global__ void gather_kernel(const float* __restrict__ x,
                              float* __restrict__ out) {
    const int row  = (blockIdx.x * blockDim.x + threadIdx.x) >> 5;
    const int lane = threadIdx.x & 31;
    const int bi = row / K;            // b*N + i
    const int b  = bi >> 12;           // N = 4096
    const int nn = g_nn[row];

    const float4* xi = (const float4*)(x + (size_t)bi * D);
    const float4* xn = (const float4*)(x + ((size_t)(b * N + nn)) * D);

    float4 v;
    if (lane < 16) {
        v = xi[lane];
    } else {
        float4 a = xn[lane - 16];
        float4 c = xi[lane - 16];
        v = make_float4(a.x - c.x, a.y - c.y, a.z - c.z, a.w - c.w);
    }
    ((float4*)out)[(size_t)row * 32 + lane] = v;
}

// ---------------------------------------------------------------------------
extern "C" void kernel_launch(void* const* d_in, const int* in_sizes, int n_in,
                              void* d_out, int out_size) {
    const float* x   = (const float*)d_in[0];
    float*       out = (float*)d_out;

    sq_kernel<<<(NQ + 255) / 256, 256>>>(x);
    knn_kernel<<<2 * NQ / 32, 32>>>(x);
    merge_kernel<<<(NQ + 255) / 256, 256>>>();
    gather_kernel<<<(NQ * K * 32) / 256, 256>>>(x, out);
}